// round 5
// baseline (speedup 1.0000x reference)
#include <cuda_runtime.h>
#include <cuda_bf16.h>

// EdgeEncoding: out[h,i,j] = sum_e coeff[e]*enc[node[e],h], enc = edge_attr@W.T+b.
// Factorized: out[h,p] = g[p].W[h] + b[h]*s[p]; g[p]=sum c_e*edge_attr[node_e], s[p]=sum c_e.
// pair_idx sorted over the real prefix; padding tail coeff==0 (flushes suppressed by s==0).
// Pass1: warp-cooperative segmented reduce-by-key, 8 chunks of 128 entries per warp.

#define NNODES 768
#define NN (NNODES * NNODES)   // 589824
#define NH 32

#define BT 256                  // threads/block pass1 (8 warps)
#define CH 8                    // 128-entry chunks per warp
#define TILE (8 * CH * 128)     // 8192 entries per block

// Fused scratch: g (float4[NN]) then s (float[NN]); zeroed by one memset node.
__device__ __align__(16) float d_buf[NN * 5];
#define D_G ((float4*)d_buf)
#define D_S (d_buf + (size_t)NN * 4)

// Branchless predicated flush (exclusive interior segments): no BSSY/BSYNC.
__device__ __forceinline__ void pred_flush(int doit, int key,
                                           float ax, float ay, float az, float aw, float as)
{
    unsigned long long ga = (unsigned long long)(D_G + key);
    unsigned long long sa = (unsigned long long)(D_S + key);
    asm volatile(
        "{\n\t.reg .pred p;\n\t"
        "setp.ne.s32 p, %0, 0;\n\t"
        "@p st.global.v4.f32 [%1], {%3, %4, %5, %6};\n\t"
        "@p st.global.f32 [%2], %7;\n\t}"
        :: "r"(doit), "l"(ga), "l"(sa),
           "f"(ax), "f"(ay), "f"(az), "f"(aw), "f"(as));
}

__device__ __forceinline__ void flush_maybe_shared(bool shared_seg, int key,
                                                   float ax, float ay, float az,
                                                   float aw, float as)
{
    float* gp = reinterpret_cast<float*>(&D_G[key]);
    if (shared_seg) {
        atomicAdd(gp + 0, ax); atomicAdd(gp + 1, ay);
        atomicAdd(gp + 2, az); atomicAdd(gp + 3, aw);
        atomicAdd(&D_S[key], as);
    } else {
        D_G[key] = make_float4(ax, ay, az, aw);
        D_S[key] = as;
    }
}

// ---------------------------------------------------------------------------
// Pass 1
// ---------------------------------------------------------------------------
__global__ void __launch_bounds__(BT) pass1_kernel(
    const int*   __restrict__ pair_idx,
    const int*   __restrict__ node_idx,
    const float* __restrict__ coeff,
    const float* __restrict__ edge_attr,   // [768,4]
    int M)
{
    const int tile0 = blockIdx.x * TILE;
    // Skip all-padding blocks (real coeffs strictly positive, padding is a suffix).
    if (tile0 > 0 && tile0 < M && __ldg(&coeff[tile0]) == 0.f) return;

    __shared__ float4 sea[NNODES];   // 12 KB
    const int tid = threadIdx.x;
    for (int i = tid; i < NNODES; i += BT)
        sea[i] = reinterpret_cast<const float4*>(edge_attr)[i];
    __syncthreads();

    const int lane = tid & 31;
    const int warp = tid >> 5;
    const unsigned FULL = 0xffffffffu;

    for (int c = 0; c < CH; c++) {
        const int base = tile0 + (warp * CH + c) * 128;   // warp-uniform
        if (base >= M) break;
        const int e0 = base + lane * 4;

        // --- load 4 entries (coalesced int4) ---
        int pk0, pk1, pk2, pk3, nk0, nk1, nk2, nk3;
        float c0, c1, c2, c3;
        if (base + 128 <= M) {
            int4   pv = __ldg(reinterpret_cast<const int4*>(pair_idx + e0));
            int4   nv = __ldg(reinterpret_cast<const int4*>(node_idx + e0));
            float4 cv = __ldg(reinterpret_cast<const float4*>(coeff + e0));
            pk0 = pv.x; pk1 = pv.y; pk2 = pv.z; pk3 = pv.w;
            nk0 = nv.x; nk1 = nv.y; nk2 = nv.z; nk3 = nv.w;
            c0 = cv.x; c1 = cv.y; c2 = cv.z; c3 = cv.w;
        } else {
            int tp[4]; int tn[4]; float tc[4];
            #pragma unroll
            for (int k = 0; k < 4; k++) {
                int g = e0 + k;
                bool ok = (g < M);
                tp[k] = ok ? __ldg(&pair_idx[g]) : 0;
                tn[k] = ok ? __ldg(&node_idx[g]) : 0;
                tc[k] = ok ? __ldg(&coeff[g])    : 0.f;
            }
            pk0 = tp[0]; pk1 = tp[1]; pk2 = tp[2]; pk3 = tp[3];
            nk0 = tn[0]; nk1 = tn[1]; nk2 = tn[2]; nk3 = tn[3];
            c0 = tc[0]; c1 = tc[1]; c2 = tc[2]; c3 = tc[3];
        }

        // warp neighbor keys
        int pv0 = 0;
        if (lane == 0)  pv0 = (base > 0) ? __ldg(&pair_idx[base - 1]) : -3;
        const int prevk = __shfl_sync(FULL, pv0, 0);
        int nv31 = 0;
        if (lane == 31) nv31 = (base + 128 < M) ? __ldg(&pair_idx[base + 128]) : -3;
        const int nextk = __shfl_sync(FULL, nv31, 31);

        // --- local scan of 4 items ---
        const int headkey = pk0;
        int   cur = pk0;
        float4 ea0 = sea[nk0];
        float ax = c0 * ea0.x, ay = c0 * ea0.y, az = c0 * ea0.z, aw = c0 * ea0.w, as = c0;
        int   segcnt = 0;
        int   hkey = 0;
        float hx = 0.f, hy = 0.f, hz = 0.f, hw = 0.f, hs = 0.f;

        int kk_[3] = {pk1, pk2, pk3};
        int nn_[3] = {nk1, nk2, nk3};
        float cc_[3] = {c1, c2, c3};
        #pragma unroll
        for (int k = 0; k < 3; k++) {
            int  key = kk_[k];
            bool neq = (key != cur);
            // interior segment (2nd+ change): fully inside lane => exclusive store
            int doflush = (int)(neq & (segcnt > 0) & (as != 0.f));
            pred_flush(doflush, cur, ax, ay, az, aw, as);
            // stash first segment partial (connects left)
            bool stash = neq & (segcnt == 0);
            hkey = stash ? cur : hkey;
            hx = stash ? ax : hx; hy = stash ? ay : hy; hz = stash ? az : hz;
            hw = stash ? aw : hw; hs = stash ? as : hs;
            segcnt += (int)neq;
            float  cc = cc_[k];
            float4 e  = sea[nn_[k]];
            ax = fmaf(cc, e.x, neq ? 0.f : ax);
            ay = fmaf(cc, e.y, neq ? 0.f : ay);
            az = fmaf(cc, e.z, neq ? 0.f : az);
            aw = fmaf(cc, e.w, neq ? 0.f : aw);
            as = cc + (neq ? 0.f : as);
            cur = key;
        }
        const int tkey = cur;   // trailing segment key; (ax..as) = trailing partial

        // --- conditional Kogge-Stone over equal-tkey runs ---
        #pragma unroll
        for (int d = 1; d < 32; d <<= 1) {
            int   sk = __shfl_up_sync(FULL, tkey, d);
            float sx = __shfl_up_sync(FULL, ax, d);
            float sy = __shfl_up_sync(FULL, ay, d);
            float sz = __shfl_up_sync(FULL, az, d);
            float sw = __shfl_up_sync(FULL, aw, d);
            float ss = __shfl_up_sync(FULL, as, d);
            bool add = (lane >= d) && (sk == tkey);
            ax += add ? sx : 0.f;
            ay += add ? sy : 0.f;
            az += add ? sz : 0.f;
            aw += add ? sw : 0.f;
            as += add ? ss : 0.f;
        }

        int   tkp = __shfl_up_sync(FULL, tkey, 1);
        float ypx = __shfl_up_sync(FULL, ax, 1);
        float ypy = __shfl_up_sync(FULL, ay, 1);
        float ypz = __shfl_up_sync(FULL, az, 1);
        float ypw = __shfl_up_sync(FULL, aw, 1);
        float yps = __shfl_up_sync(FULL, as, 1);
        int   hkn = __shfl_down_sync(FULL, headkey, 1);

        // 1) head-close flush (impure lanes): first segment closed in this lane.
        if (segcnt > 0) {
            bool cge = (lane > 0) && (hkey == tkp);
            float fx = hx + (cge ? ypx : 0.f);
            float fy = hy + (cge ? ypy : 0.f);
            float fz = hz + (cge ? ypz : 0.f);
            float fw = hw + (cge ? ypw : 0.f);
            float fs = hs + (cge ? yps : 0.f);
            if (fs != 0.f)
                flush_maybe_shared(hkey == prevk, hkey, fx, fy, fz, fw, fs);
        }
        // 2) trailing-chain close.
        bool closes = (lane == 31) || (hkn != tkey);
        if (closes && as != 0.f) {
            bool shared_seg = (tkey == prevk) || ((lane == 31) && (tkey == nextk));
            flush_maybe_shared(shared_seg, tkey, ax, ay, az, aw, as);
        }
    }
}

// ---------------------------------------------------------------------------
// Pass 2: expand g/s -> 32 channels, plane-major coalesced float4 stores.
// ---------------------------------------------------------------------------
#define BT2 128
#define PP  4

__global__ void __launch_bounds__(BT2) pass2_kernel(
    const float* __restrict__ W,   // [32,4]
    const float* __restrict__ b,   // [32]
    float* __restrict__ out)       // [32, 768*768]
{
    __shared__ float sW[NH * 4];
    __shared__ float sb[NH];
    int tid = threadIdx.x;
    if (tid < NH * 4) sW[tid] = W[tid];
    if (tid < NH)     sb[tid] = b[tid];
    __syncthreads();

    int p = (blockIdx.x * BT2 + tid) * PP;
    float4 g0 = __ldcs(&D_G[p + 0]);
    float4 g1 = __ldcs(&D_G[p + 1]);
    float4 g2 = __ldcs(&D_G[p + 2]);
    float4 g3 = __ldcs(&D_G[p + 3]);
    float4 sv = __ldcs(reinterpret_cast<const float4*>(D_S) + (p >> 2));

    #pragma unroll 8
    for (int h = 0; h < NH; h++) {
        float w0 = sW[4 * h + 0], w1 = sW[4 * h + 1];
        float w2 = sW[4 * h + 2], w3 = sW[4 * h + 3];
        float bh = sb[h];
        float4 r;
        r.x = fmaf(g0.x, w0, fmaf(g0.y, w1, fmaf(g0.z, w2, fmaf(g0.w, w3, sv.x * bh))));
        r.y = fmaf(g1.x, w0, fmaf(g1.y, w1, fmaf(g1.z, w2, fmaf(g1.w, w3, sv.y * bh))));
        r.z = fmaf(g2.x, w0, fmaf(g2.y, w1, fmaf(g2.z, w2, fmaf(g2.w, w3, sv.z * bh))));
        r.w = fmaf(g3.x, w0, fmaf(g3.y, w1, fmaf(g3.z, w2, fmaf(g3.w, w3, sv.w * bh))));
        __stcs(reinterpret_cast<float4*>(out) + ((h * NN + p) >> 2), r);
    }
}

// ---------------------------------------------------------------------------
// kernel_launch
// ---------------------------------------------------------------------------
extern "C" void kernel_launch(void* const* d_in, const int* in_sizes, int n_in,
                              void* d_out, int out_size)
{
    const float* edge_attr = nullptr;
    const float* W = nullptr;
    const float* b = nullptr;
    const int*   pair = nullptr;
    const int*   node = nullptr;
    const float* coeff = nullptr;
    int M = 0;
    int bigSeen = 0;

    for (int i = 0; i < n_in; i++) {
        int s = in_sizes[i];
        if (s == NNODES * 4)      edge_attr = (const float*)d_in[i];
        else if (s == NH * 4)     W = (const float*)d_in[i];
        else if (s == NH)         b = (const float*)d_in[i];
        else if (s >= 1000000) {
            if (bigSeen == 0)      pair  = (const int*)d_in[i];
            else if (bigSeen == 1) node  = (const int*)d_in[i];
            else if (bigSeen == 2) { coeff = (const float*)d_in[i]; M = s; }
            bigSeen++;
        }
    }

    // Zero scratch with a graph-capturable memset node (no allocation).
    void* bufp = nullptr;
    cudaGetSymbolAddress(&bufp, d_buf);
    cudaMemsetAsync(bufp, 0, sizeof(float) * (size_t)NN * 5);

    int grid1 = (M + TILE - 1) / TILE;   // ~1221
    pass1_kernel<<<grid1, BT>>>(pair, node, coeff, edge_attr, M);

    int grid2 = NN / (BT2 * PP);         // 1152
    pass2_kernel<<<grid2, BT2>>>(W, b, (float*)d_out);
}

// round 6
// speedup vs baseline: 1.0774x; 1.0774x over previous
#include <cuda_runtime.h>
#include <cuda_bf16.h>

// EdgeEncoding: out[h,i,j] = sum_e coeff[e]*enc[node[e],h], enc = edge_attr@W.T+b.
// Factorized: out[h,p] = g[p].W[h] + b[h]*s[p]; g[p]=sum c_e*edge_attr[node_e], s[p]=sum c_e.
// pair_idx sorted over the real prefix; padding tail coeff==0 (flushes suppressed by s==0).
// Pass1: warp-cooperative segmented reduce-by-key; 2 prefetched 128-entry chunks per warp.

#define NNODES 768
#define NN (NNODES * NNODES)   // 589824
#define NH 32

#define BT 256                  // 8 warps
#define CH 2                    // chunks per warp (software-pipelined)
#define TILE ((BT / 32) * CH * 128)   // 2048 entries/block

// Fused scratch: g (float4[NN]) then s (float[NN]); zeroed by one memset node.
__device__ __align__(16) float d_buf[NN * 5];
#define D_G ((float4*)d_buf)
#define D_S (d_buf + (size_t)NN * 4)

// Branchless predicated flush (exclusive interior segments): no BSSY/BSYNC.
__device__ __forceinline__ void pred_flush(int doit, int key,
                                           float ax, float ay, float az, float aw, float as)
{
    unsigned long long ga = (unsigned long long)(D_G + key);
    unsigned long long sa = (unsigned long long)(D_S + key);
    asm volatile(
        "{\n\t.reg .pred p;\n\t"
        "setp.ne.s32 p, %0, 0;\n\t"
        "@p st.global.v4.f32 [%1], {%3, %4, %5, %6};\n\t"
        "@p st.global.f32 [%2], %7;\n\t}"
        :: "r"(doit), "l"(ga), "l"(sa),
           "f"(ax), "f"(ay), "f"(az), "f"(aw), "f"(as));
}

__device__ __forceinline__ void flush_maybe_shared(bool shared_seg, int key,
                                                   float ax, float ay, float az,
                                                   float aw, float as)
{
    float* gp = reinterpret_cast<float*>(&D_G[key]);
    if (shared_seg) {
        atomicAdd(gp + 0, ax); atomicAdd(gp + 1, ay);
        atomicAdd(gp + 2, az); atomicAdd(gp + 3, aw);
        atomicAdd(&D_S[key], as);
    } else {
        D_G[key] = make_float4(ax, ay, az, aw);
        D_S[key] = as;
    }
}

struct Chunk {
    int   pk[4];
    int   nk[4];
    float ck[4];
};

__device__ __forceinline__ void load_chunk(Chunk& C, int base, int lane,
                                           const int* __restrict__ pair_idx,
                                           const int* __restrict__ node_idx,
                                           const float* __restrict__ coeff,
                                           int M)
{
    const int e0 = base + lane * 4;
    if (base + 128 <= M) {
        int4   pv = __ldg(reinterpret_cast<const int4*>(pair_idx + e0));
        int4   nv = __ldg(reinterpret_cast<const int4*>(node_idx + e0));
        float4 cv = __ldg(reinterpret_cast<const float4*>(coeff + e0));
        C.pk[0] = pv.x; C.pk[1] = pv.y; C.pk[2] = pv.z; C.pk[3] = pv.w;
        C.nk[0] = nv.x; C.nk[1] = nv.y; C.nk[2] = nv.z; C.nk[3] = nv.w;
        C.ck[0] = cv.x; C.ck[1] = cv.y; C.ck[2] = cv.z; C.ck[3] = cv.w;
    } else {
        #pragma unroll
        for (int k = 0; k < 4; k++) {
            int g = e0 + k;
            bool ok = (g < M);
            C.pk[k] = ok ? __ldg(&pair_idx[g]) : 0;
            C.nk[k] = ok ? __ldg(&node_idx[g]) : 0;
            C.ck[k] = ok ? __ldg(&coeff[g])    : 0.f;
        }
    }
}

// Process one 128-entry warp chunk: per-lane scan of 4 items + conditional
// Kogge-Stone across lanes; interior segments -> predicated exclusive stores;
// boundary-touching segments -> atomics.
__device__ __forceinline__ void process_chunk(const Chunk& C, int lane,
                                              int prevk, int nextk,
                                              const float4* __restrict__ sea)
{
    const unsigned FULL = 0xffffffffu;

    const int headkey = C.pk[0];
    int   cur = C.pk[0];
    float4 ea0 = sea[C.nk[0]];
    float c0 = C.ck[0];
    float ax = c0 * ea0.x, ay = c0 * ea0.y, az = c0 * ea0.z, aw = c0 * ea0.w, as = c0;
    int   segcnt = 0;
    int   hkey = 0;
    float hx = 0.f, hy = 0.f, hz = 0.f, hw = 0.f, hs = 0.f;

    #pragma unroll
    for (int k = 1; k < 4; k++) {
        int  key = C.pk[k];
        bool neq = (key != cur);
        int doflush = (int)(neq & (segcnt > 0) & (as != 0.f));
        pred_flush(doflush, cur, ax, ay, az, aw, as);
        bool stash = neq & (segcnt == 0);
        hkey = stash ? cur : hkey;
        hx = stash ? ax : hx; hy = stash ? ay : hy; hz = stash ? az : hz;
        hw = stash ? aw : hw; hs = stash ? as : hs;
        segcnt += (int)neq;
        float  cc = C.ck[k];
        float4 e  = sea[C.nk[k]];
        ax = fmaf(cc, e.x, neq ? 0.f : ax);
        ay = fmaf(cc, e.y, neq ? 0.f : ay);
        az = fmaf(cc, e.z, neq ? 0.f : az);
        aw = fmaf(cc, e.w, neq ? 0.f : aw);
        as = cc + (neq ? 0.f : as);
        cur = key;
    }
    const int tkey = cur;   // trailing key; (ax..as) = trailing partial

    #pragma unroll
    for (int d = 1; d < 32; d <<= 1) {
        int   sk = __shfl_up_sync(FULL, tkey, d);
        float sx = __shfl_up_sync(FULL, ax, d);
        float sy = __shfl_up_sync(FULL, ay, d);
        float sz = __shfl_up_sync(FULL, az, d);
        float sw = __shfl_up_sync(FULL, aw, d);
        float ss = __shfl_up_sync(FULL, as, d);
        bool add = (lane >= d) && (sk == tkey);
        ax += add ? sx : 0.f;
        ay += add ? sy : 0.f;
        az += add ? sz : 0.f;
        aw += add ? sw : 0.f;
        as += add ? ss : 0.f;
    }

    int   tkp = __shfl_up_sync(FULL, tkey, 1);
    float ypx = __shfl_up_sync(FULL, ax, 1);
    float ypy = __shfl_up_sync(FULL, ay, 1);
    float ypz = __shfl_up_sync(FULL, az, 1);
    float ypw = __shfl_up_sync(FULL, aw, 1);
    float yps = __shfl_up_sync(FULL, as, 1);
    int   hkn = __shfl_down_sync(FULL, headkey, 1);

    // head-close flush: first segment of this lane closed inside the lane.
    if (segcnt > 0) {
        bool cge = (lane > 0) && (hkey == tkp);
        float fx = hx + (cge ? ypx : 0.f);
        float fy = hy + (cge ? ypy : 0.f);
        float fz = hz + (cge ? ypz : 0.f);
        float fw = hw + (cge ? ypw : 0.f);
        float fs = hs + (cge ? yps : 0.f);
        if (fs != 0.f)
            flush_maybe_shared(hkey == prevk, hkey, fx, fy, fz, fw, fs);
    }
    // trailing-chain close: this lane holds the full within-chunk sum for tkey.
    bool closes = (lane == 31) || (hkn != tkey);
    if (closes && as != 0.f) {
        bool shared_seg = (tkey == prevk) || ((lane == 31) && (tkey == nextk));
        flush_maybe_shared(shared_seg, tkey, ax, ay, az, aw, as);
    }
}

// ---------------------------------------------------------------------------
// Pass 1
// ---------------------------------------------------------------------------
__global__ void __launch_bounds__(BT) pass1_kernel(
    const int*   __restrict__ pair_idx,
    const int*   __restrict__ node_idx,
    const float* __restrict__ coeff,
    const float* __restrict__ edge_attr,   // [768,4]
    int M)
{
    const int tile0 = blockIdx.x * TILE;
    // Skip all-padding blocks (real coeffs strictly positive, padding is a suffix).
    if (tile0 > 0 && tile0 < M && __ldg(&coeff[tile0]) == 0.f) return;

    __shared__ float4 sea[NNODES];   // 12 KB
    const int tid = threadIdx.x;
    for (int i = tid; i < NNODES; i += BT)
        sea[i] = reinterpret_cast<const float4*>(edge_attr)[i];
    __syncthreads();

    const int lane  = tid & 31;
    const int warp  = tid >> 5;
    const unsigned FULL = 0xffffffffu;

    const int base0 = tile0 + warp * (CH * 128);
    if (base0 >= M) return;
    const int base1 = base0 + 128;
    const bool has1 = (base1 < M);

    // ---- prefetch everything: both chunks + outer boundary keys ----
    Chunk A, B;
    load_chunk(A, base0, lane, pair_idx, node_idx, coeff, M);
    if (has1) load_chunk(B, base1, lane, pair_idx, node_idx, coeff, M);

    int pv0 = 0;
    if (lane == 0)  pv0 = (base0 > 0) ? __ldg(&pair_idx[base0 - 1]) : -3;
    const int prev0 = __shfl_sync(FULL, pv0, 0);
    int nv31 = 0;
    if (lane == 31) nv31 = (base1 + 128 < M) ? __ldg(&pair_idx[base1 + 128]) : -3;
    const int next1 = __shfl_sync(FULL, nv31, 31);

    // inner boundary keys come from registers
    const int next0 = has1 ? __shfl_sync(FULL, B.pk[0], 0)
                           : ((base1 < M) ? -2 : -3);   // has1 == (base1<M), so just -3
    const int prev1 = __shfl_sync(FULL, A.pk[3], 31);

    process_chunk(A, lane, prev0, has1 ? next0 : -3, sea);
    if (has1) process_chunk(B, lane, prev1, next1, sea);
}

// ---------------------------------------------------------------------------
// Pass 2: expand g/s -> 32 channels, plane-major coalesced float4 stores.
// ---------------------------------------------------------------------------
#define BT2 128
#define PP  4

__global__ void __launch_bounds__(BT2) pass2_kernel(
    const float* __restrict__ W,   // [32,4]
    const float* __restrict__ b,   // [32]
    float* __restrict__ out)       // [32, 768*768]
{
    __shared__ float sW[NH * 4];
    __shared__ float sb[NH];
    int tid = threadIdx.x;
    if (tid < NH * 4) sW[tid] = W[tid];
    if (tid < NH)     sb[tid] = b[tid];
    __syncthreads();

    int p = (blockIdx.x * BT2 + tid) * PP;
    float4 g0 = __ldcs(&D_G[p + 0]);
    float4 g1 = __ldcs(&D_G[p + 1]);
    float4 g2 = __ldcs(&D_G[p + 2]);
    float4 g3 = __ldcs(&D_G[p + 3]);
    float4 sv = __ldcs(reinterpret_cast<const float4*>(D_S) + (p >> 2));

    #pragma unroll 8
    for (int h = 0; h < NH; h++) {
        float w0 = sW[4 * h + 0], w1 = sW[4 * h + 1];
        float w2 = sW[4 * h + 2], w3 = sW[4 * h + 3];
        float bh = sb[h];
        float4 r;
        r.x = fmaf(g0.x, w0, fmaf(g0.y, w1, fmaf(g0.z, w2, fmaf(g0.w, w3, sv.x * bh))));
        r.y = fmaf(g1.x, w0, fmaf(g1.y, w1, fmaf(g1.z, w2, fmaf(g1.w, w3, sv.y * bh))));
        r.z = fmaf(g2.x, w0, fmaf(g2.y, w1, fmaf(g2.z, w2, fmaf(g2.w, w3, sv.z * bh))));
        r.w = fmaf(g3.x, w0, fmaf(g3.y, w1, fmaf(g3.z, w2, fmaf(g3.w, w3, sv.w * bh))));
        __stcs(reinterpret_cast<float4*>(out) + ((h * NN + p) >> 2), r);
    }
}

// ---------------------------------------------------------------------------
// kernel_launch
// ---------------------------------------------------------------------------
extern "C" void kernel_launch(void* const* d_in, const int* in_sizes, int n_in,
                              void* d_out, int out_size)
{
    const float* edge_attr = nullptr;
    const float* W = nullptr;
    const float* b = nullptr;
    const int*   pair = nullptr;
    const int*   node = nullptr;
    const float* coeff = nullptr;
    int M = 0;
    int bigSeen = 0;

    for (int i = 0; i < n_in; i++) {
        int s = in_sizes[i];
        if (s == NNODES * 4)      edge_attr = (const float*)d_in[i];
        else if (s == NH * 4)     W = (const float*)d_in[i];
        else if (s == NH)         b = (const float*)d_in[i];
        else if (s >= 1000000) {
            if (bigSeen == 0)      pair  = (const int*)d_in[i];
            else if (bigSeen == 1) node  = (const int*)d_in[i];
            else if (bigSeen == 2) { coeff = (const float*)d_in[i]; M = s; }
            bigSeen++;
        }
    }

    // Zero scratch with a graph-capturable memset node (no allocation).
    void* bufp = nullptr;
    cudaGetSymbolAddress(&bufp, d_buf);
    cudaMemsetAsync(bufp, 0, sizeof(float) * (size_t)NN * 5);

    int grid1 = (M + TILE - 1) / TILE;   // ~4883
    pass1_kernel<<<grid1, BT>>>(pair, node, coeff, edge_attr, M);

    int grid2 = NN / (BT2 * PP);         // 1152
    pass2_kernel<<<grid2, BT2>>>(W, b, (float*)d_out);
}

// round 7
// speedup vs baseline: 1.1364x; 1.0547x over previous
#include <cuda_runtime.h>
#include <cuda_bf16.h>

// EdgeEncoding: out[h,i,j] = sum_e coeff[e]*enc[node[e],h], enc = edge_attr@W.T+b.
// Factorized: out[h,p] = g[p].W[h] + b[h]*s[p]; g[p]=sum c_e*edge_attr[node_e], s[p]=sum c_e.
// pair_idx sorted over the real prefix; padding tail coeff==0 (flushes suppressed by s==0).
// Pass1: warp-cooperative segmented reduce-by-key, 8 items/lane (256-entry chunks),
// Kogge-Stone truncated by a warp-uniform run-length probe (segments are short:
// <=3 shortest paths * ~6 nodes => <=~21 entries <= 3 lanes).

#define NNODES 768
#define NN (NNODES * NNODES)   // 589824
#define NH 32

#define BT 256                  // 8 warps
#define IPL 8                   // items per lane
#define CHUNK (32 * IPL)        // 256 entries per warp
#define TILE ((BT / 32) * CHUNK) // 2048 entries per block

// Fused scratch: g (float4[NN]) then s (float[NN]); zeroed by one memset node.
__device__ __align__(16) float d_buf[NN * 5];
#define D_G ((float4*)d_buf)
#define D_S (d_buf + (size_t)NN * 4)

// Branchless predicated flush (exclusive interior segments): no BSSY/BSYNC.
__device__ __forceinline__ void pred_flush(int doit, int key,
                                           float ax, float ay, float az, float aw, float as)
{
    unsigned long long ga = (unsigned long long)(D_G + key);
    unsigned long long sa = (unsigned long long)(D_S + key);
    asm volatile(
        "{\n\t.reg .pred p;\n\t"
        "setp.ne.s32 p, %0, 0;\n\t"
        "@p st.global.v4.f32 [%1], {%3, %4, %5, %6};\n\t"
        "@p st.global.f32 [%2], %7;\n\t}"
        :: "r"(doit), "l"(ga), "l"(sa),
           "f"(ax), "f"(ay), "f"(az), "f"(aw), "f"(as));
}

__device__ __forceinline__ void flush_maybe_shared(bool shared_seg, int key,
                                                   float ax, float ay, float az,
                                                   float aw, float as)
{
    float* gp = reinterpret_cast<float*>(&D_G[key]);
    if (shared_seg) {
        atomicAdd(gp + 0, ax); atomicAdd(gp + 1, ay);
        atomicAdd(gp + 2, az); atomicAdd(gp + 3, aw);
        atomicAdd(&D_S[key], as);
    } else {
        D_G[key] = make_float4(ax, ay, az, aw);
        D_S[key] = as;
    }
}

// One Kogge-Stone step over the 5-float partial, conditional on equal keys.
#define KS_STEP(d)                                                         \
    do {                                                                   \
        int   sk = __shfl_up_sync(FULL, tkey, d);                          \
        float sx = __shfl_up_sync(FULL, ax, d);                            \
        float sy = __shfl_up_sync(FULL, ay, d);                            \
        float sz = __shfl_up_sync(FULL, az, d);                            \
        float sw = __shfl_up_sync(FULL, aw, d);                            \
        float ss = __shfl_up_sync(FULL, as, d);                            \
        bool add = (lane >= d) && (sk == tkey);                            \
        ax += add ? sx : 0.f;                                              \
        ay += add ? sy : 0.f;                                              \
        az += add ? sz : 0.f;                                              \
        aw += add ? sw : 0.f;                                              \
        as += add ? ss : 0.f;                                              \
    } while (0)

// ---------------------------------------------------------------------------
// Pass 1
// ---------------------------------------------------------------------------
__global__ void __launch_bounds__(BT) pass1_kernel(
    const int*   __restrict__ pair_idx,
    const int*   __restrict__ node_idx,
    const float* __restrict__ coeff,
    const float* __restrict__ edge_attr,   // [768,4]
    int M)
{
    const int tile0 = blockIdx.x * TILE;
    // Skip all-padding blocks (real coeffs strictly positive, padding is a suffix).
    if (tile0 > 0 && tile0 < M && __ldg(&coeff[tile0]) == 0.f) return;

    __shared__ float4 sea[NNODES];   // 12 KB
    const int tid = threadIdx.x;
    for (int i = tid; i < NNODES; i += BT)
        sea[i] = reinterpret_cast<const float4*>(edge_attr)[i];
    __syncthreads();

    const int lane = tid & 31;
    const int warp = tid >> 5;
    const unsigned FULL = 0xffffffffu;

    const int base = tile0 + warp * CHUNK;
    if (base >= M) return;
    const int e0 = base + lane * IPL;

    // --- load 8 entries: 2 x int4 per array ---
    int   pk[IPL], nk[IPL];
    float ck[IPL];
    if (base + CHUNK <= M) {
        #pragma unroll
        for (int h = 0; h < 2; h++) {
            int4   pv = __ldg(reinterpret_cast<const int4*>(pair_idx + e0) + h);
            int4   nv = __ldg(reinterpret_cast<const int4*>(node_idx + e0) + h);
            float4 cv = __ldg(reinterpret_cast<const float4*>(coeff + e0) + h);
            pk[4*h+0] = pv.x; pk[4*h+1] = pv.y; pk[4*h+2] = pv.z; pk[4*h+3] = pv.w;
            nk[4*h+0] = nv.x; nk[4*h+1] = nv.y; nk[4*h+2] = nv.z; nk[4*h+3] = nv.w;
            ck[4*h+0] = cv.x; ck[4*h+1] = cv.y; ck[4*h+2] = cv.z; ck[4*h+3] = cv.w;
        }
    } else {
        #pragma unroll
        for (int k = 0; k < IPL; k++) {
            int g = e0 + k;
            bool ok = (g < M);
            pk[k] = ok ? __ldg(&pair_idx[g]) : 0;
            nk[k] = ok ? __ldg(&node_idx[g]) : 0;
            ck[k] = ok ? __ldg(&coeff[g])    : 0.f;
        }
    }

    // warp neighbor keys
    int pv0 = 0;
    if (lane == 0)  pv0 = (base > 0) ? __ldg(&pair_idx[base - 1]) : -3;
    const int prevk = __shfl_sync(FULL, pv0, 0);
    int nv31 = 0;
    if (lane == 31) nv31 = (base + CHUNK < M) ? __ldg(&pair_idx[base + CHUNK]) : -3;
    const int nextk = __shfl_sync(FULL, nv31, 31);

    // --- per-lane scan of 8 items ---
    const int headkey = pk[0];
    int   cur = pk[0];
    float4 ea0 = sea[nk[0]];
    float c0 = ck[0];
    float ax = c0 * ea0.x, ay = c0 * ea0.y, az = c0 * ea0.z, aw = c0 * ea0.w, as = c0;
    int   segcnt = 0;
    int   hkey = 0;
    float hx = 0.f, hy = 0.f, hz = 0.f, hw = 0.f, hs = 0.f;

    #pragma unroll
    for (int k = 1; k < IPL; k++) {
        int  key = pk[k];
        bool neq = (key != cur);
        // interior segment (2nd+ change): fully inside lane => exclusive store
        int doflush = (int)(neq & (segcnt > 0) & (as != 0.f));
        pred_flush(doflush, cur, ax, ay, az, aw, as);
        // stash first segment partial (connects left)
        bool stash = neq & (segcnt == 0);
        hkey = stash ? cur : hkey;
        hx = stash ? ax : hx; hy = stash ? ay : hy; hz = stash ? az : hz;
        hw = stash ? aw : hw; hs = stash ? as : hs;
        segcnt += (int)neq;
        float  cc = ck[k];
        float4 e  = sea[nk[k]];
        ax = fmaf(cc, e.x, neq ? 0.f : ax);
        ay = fmaf(cc, e.y, neq ? 0.f : ay);
        az = fmaf(cc, e.z, neq ? 0.f : az);
        aw = fmaf(cc, e.w, neq ? 0.f : aw);
        as = cc + (neq ? 0.f : as);
        cur = key;
    }
    const int tkey = cur;   // trailing key; (ax..as) = trailing partial

    // --- Kogge-Stone with warp-uniform truncation.
    // Segments are typically <= ~21 entries (<= 3 lanes at 8/lane), so runs
    // longer than 4 lanes are rare: probe before d=4 and beyond.
    KS_STEP(1);
    KS_STEP(2);
    {
        int k4 = __shfl_up_sync(FULL, tkey, 4);
        if (__any_sync(FULL, (lane >= 4) && (k4 == tkey))) {
            KS_STEP(4);
            int k8 = __shfl_up_sync(FULL, tkey, 8);
            if (__any_sync(FULL, (lane >= 8) && (k8 == tkey))) {
                KS_STEP(8);
                KS_STEP(16);
            }
        }
    }

    int   tkp = __shfl_up_sync(FULL, tkey, 1);
    float ypx = __shfl_up_sync(FULL, ax, 1);
    float ypy = __shfl_up_sync(FULL, ay, 1);
    float ypz = __shfl_up_sync(FULL, az, 1);
    float ypw = __shfl_up_sync(FULL, aw, 1);
    float yps = __shfl_up_sync(FULL, as, 1);
    int   hkn = __shfl_down_sync(FULL, headkey, 1);

    // 1) head-close flush: first segment of this lane closed inside the lane.
    if (segcnt > 0) {
        bool cge = (lane > 0) && (hkey == tkp);
        float fx = hx + (cge ? ypx : 0.f);
        float fy = hy + (cge ? ypy : 0.f);
        float fz = hz + (cge ? ypz : 0.f);
        float fw = hw + (cge ? ypw : 0.f);
        float fs = hs + (cge ? yps : 0.f);
        if (fs != 0.f)
            flush_maybe_shared(hkey == prevk, hkey, fx, fy, fz, fw, fs);
    }
    // 2) trailing-chain close: this lane holds the full within-chunk sum for tkey.
    bool closes = (lane == 31) || (hkn != tkey);
    if (closes && as != 0.f) {
        bool shared_seg = (tkey == prevk) || ((lane == 31) && (tkey == nextk));
        flush_maybe_shared(shared_seg, tkey, ax, ay, az, aw, as);
    }
}

// ---------------------------------------------------------------------------
// Pass 2: expand g/s -> 32 channels, plane-major coalesced float4 stores.
// ---------------------------------------------------------------------------
#define BT2 128
#define PP  4

__global__ void __launch_bounds__(BT2) pass2_kernel(
    const float* __restrict__ W,   // [32,4]
    const float* __restrict__ b,   // [32]
    float* __restrict__ out)       // [32, 768*768]
{
    __shared__ float sW[NH * 4];
    __shared__ float sb[NH];
    int tid = threadIdx.x;
    if (tid < NH * 4) sW[tid] = W[tid];
    if (tid < NH)     sb[tid] = b[tid];
    __syncthreads();

    int p = (blockIdx.x * BT2 + tid) * PP;
    float4 g0 = __ldcs(&D_G[p + 0]);
    float4 g1 = __ldcs(&D_G[p + 1]);
    float4 g2 = __ldcs(&D_G[p + 2]);
    float4 g3 = __ldcs(&D_G[p + 3]);
    float4 sv = __ldcs(reinterpret_cast<const float4*>(D_S) + (p >> 2));

    #pragma unroll 8
    for (int h = 0; h < NH; h++) {
        float w0 = sW[4 * h + 0], w1 = sW[4 * h + 1];
        float w2 = sW[4 * h + 2], w3 = sW[4 * h + 3];
        float bh = sb[h];
        float4 r;
        r.x = fmaf(g0.x, w0, fmaf(g0.y, w1, fmaf(g0.z, w2, fmaf(g0.w, w3, sv.x * bh))));
        r.y = fmaf(g1.x, w0, fmaf(g1.y, w1, fmaf(g1.z, w2, fmaf(g1.w, w3, sv.y * bh))));
        r.z = fmaf(g2.x, w0, fmaf(g2.y, w1, fmaf(g2.z, w2, fmaf(g2.w, w3, sv.z * bh))));
        r.w = fmaf(g3.x, w0, fmaf(g3.y, w1, fmaf(g3.z, w2, fmaf(g3.w, w3, sv.w * bh))));
        __stcs(reinterpret_cast<float4*>(out) + ((h * NN + p) >> 2), r);
    }
}

// ---------------------------------------------------------------------------
// kernel_launch
// ---------------------------------------------------------------------------
extern "C" void kernel_launch(void* const* d_in, const int* in_sizes, int n_in,
                              void* d_out, int out_size)
{
    const float* edge_attr = nullptr;
    const float* W = nullptr;
    const float* b = nullptr;
    const int*   pair = nullptr;
    const int*   node = nullptr;
    const float* coeff = nullptr;
    int M = 0;
    int bigSeen = 0;

    for (int i = 0; i < n_in; i++) {
        int s = in_sizes[i];
        if (s == NNODES * 4)      edge_attr = (const float*)d_in[i];
        else if (s == NH * 4)     W = (const float*)d_in[i];
        else if (s == NH)         b = (const float*)d_in[i];
        else if (s >= 1000000) {
            if (bigSeen == 0)      pair  = (const int*)d_in[i];
            else if (bigSeen == 1) node  = (const int*)d_in[i];
            else if (bigSeen == 2) { coeff = (const float*)d_in[i]; M = s; }
            bigSeen++;
        }
    }

    // Zero scratch with a graph-capturable memset node (no allocation).
    void* bufp = nullptr;
    cudaGetSymbolAddress(&bufp, d_buf);
    cudaMemsetAsync(bufp, 0, sizeof(float) * (size_t)NN * 5);

    int grid1 = (M + TILE - 1) / TILE;   // ~4883
    pass1_kernel<<<grid1, BT>>>(pair, node, coeff, edge_attr, M);

    int grid2 = NN / (BT2 * PP);         // 1152
    pass2_kernel<<<grid2, BT2>>>(W, b, (float*)d_out);
}

// round 8
// speedup vs baseline: 1.1404x; 1.0036x over previous
#include <cuda_runtime.h>
#include <cuda_bf16.h>

// EdgeEncoding: out[h,i,j] = sum_e coeff[e]*enc[node[e],h], enc = edge_attr@W.T+b.
// Factorized: out[h,p] = g[p].W[h] + b[h]*s[p]; g[p]=sum c_e*edge_attr[node_e], s[p]=sum c_e.
// pair_idx sorted over the real prefix; padding tail coeff==0 (flushes suppressed by s==0).
// Pass1: warp-cooperative segmented reduce-by-key, 8 items/lane (256-entry chunks),
// Kogge-Stone truncated by warp-uniform run-length probes; occupancy forced to
// 3 blocks/SM for DRAM latency hiding.

#define NNODES 768
#define NN (NNODES * NNODES)   // 589824
#define NH 32

#define BT 256                  // 8 warps
#define IPL 8                   // items per lane
#define CHUNK (32 * IPL)        // 256 entries per warp
#define TILE ((BT / 32) * CHUNK) // 2048 entries per block

// Fused scratch: g (float4[NN]) then s (float[NN]); zeroed by one memset node.
__device__ __align__(16) float d_buf[NN * 5];
#define D_G ((float4*)d_buf)
#define D_S (d_buf + (size_t)NN * 4)

// Branchless predicated flush (exclusive interior segments): no BSSY/BSYNC.
__device__ __forceinline__ void pred_flush(int doit, int key,
                                           float ax, float ay, float az, float aw, float as)
{
    unsigned long long ga = (unsigned long long)(D_G + key);
    unsigned long long sa = (unsigned long long)(D_S + key);
    asm volatile(
        "{\n\t.reg .pred p;\n\t"
        "setp.ne.s32 p, %0, 0;\n\t"
        "@p st.global.v4.f32 [%1], {%3, %4, %5, %6};\n\t"
        "@p st.global.f32 [%2], %7;\n\t}"
        :: "r"(doit), "l"(ga), "l"(sa),
           "f"(ax), "f"(ay), "f"(az), "f"(aw), "f"(as));
}

__device__ __forceinline__ void flush_maybe_shared(bool shared_seg, int key,
                                                   float ax, float ay, float az,
                                                   float aw, float as)
{
    float* gp = reinterpret_cast<float*>(&D_G[key]);
    if (shared_seg) {
        atomicAdd(gp + 0, ax); atomicAdd(gp + 1, ay);
        atomicAdd(gp + 2, az); atomicAdd(gp + 3, aw);
        atomicAdd(&D_S[key], as);
    } else {
        D_G[key] = make_float4(ax, ay, az, aw);
        D_S[key] = as;
    }
}

// One Kogge-Stone step over the 5-float partial, conditional on equal keys.
#define KS_STEP(d)                                                         \
    do {                                                                   \
        int   sk = __shfl_up_sync(FULL, tkey, d);                          \
        float sx = __shfl_up_sync(FULL, ax, d);                            \
        float sy = __shfl_up_sync(FULL, ay, d);                            \
        float sz = __shfl_up_sync(FULL, az, d);                            \
        float sw = __shfl_up_sync(FULL, aw, d);                            \
        float ss = __shfl_up_sync(FULL, as, d);                            \
        bool add = (lane >= d) && (sk == tkey);                            \
        ax += add ? sx : 0.f;                                              \
        ay += add ? sy : 0.f;                                              \
        az += add ? sz : 0.f;                                              \
        aw += add ? sw : 0.f;                                              \
        as += add ? ss : 0.f;                                              \
    } while (0)

// ---------------------------------------------------------------------------
// Pass 1
// ---------------------------------------------------------------------------
__global__ void __launch_bounds__(BT, 3) pass1_kernel(
    const int*   __restrict__ pair_idx,
    const int*   __restrict__ node_idx,
    const float* __restrict__ coeff,
    const float* __restrict__ edge_attr,   // [768,4]
    int M)
{
    const int tile0 = blockIdx.x * TILE;
    // Skip all-padding blocks (real coeffs strictly positive, padding is a suffix).
    if (tile0 > 0 && tile0 < M && __ldg(&coeff[tile0]) == 0.f) return;

    __shared__ float4 sea[NNODES];   // 12 KB
    const int tid = threadIdx.x;
    for (int i = tid; i < NNODES; i += BT)
        sea[i] = reinterpret_cast<const float4*>(edge_attr)[i];
    __syncthreads();

    const int lane = tid & 31;
    const int warp = tid >> 5;
    const unsigned FULL = 0xffffffffu;

    const int base = tile0 + warp * CHUNK;
    if (base >= M) return;
    const int e0 = base + lane * IPL;

    // --- load 8 entries: 2 x int4 per array ---
    int   pk[IPL], nk[IPL];
    float ck[IPL];
    if (base + CHUNK <= M) {
        #pragma unroll
        for (int h = 0; h < 2; h++) {
            int4   pv = __ldg(reinterpret_cast<const int4*>(pair_idx + e0) + h);
            int4   nv = __ldg(reinterpret_cast<const int4*>(node_idx + e0) + h);
            float4 cv = __ldg(reinterpret_cast<const float4*>(coeff + e0) + h);
            pk[4*h+0] = pv.x; pk[4*h+1] = pv.y; pk[4*h+2] = pv.z; pk[4*h+3] = pv.w;
            nk[4*h+0] = nv.x; nk[4*h+1] = nv.y; nk[4*h+2] = nv.z; nk[4*h+3] = nv.w;
            ck[4*h+0] = cv.x; ck[4*h+1] = cv.y; ck[4*h+2] = cv.z; ck[4*h+3] = cv.w;
        }
    } else {
        #pragma unroll
        for (int k = 0; k < IPL; k++) {
            int g = e0 + k;
            bool ok = (g < M);
            pk[k] = ok ? __ldg(&pair_idx[g]) : 0;
            nk[k] = ok ? __ldg(&node_idx[g]) : 0;
            ck[k] = ok ? __ldg(&coeff[g])    : 0.f;
        }
    }

    // warp neighbor keys
    int pv0 = 0;
    if (lane == 0)  pv0 = (base > 0) ? __ldg(&pair_idx[base - 1]) : -3;
    const int prevk = __shfl_sync(FULL, pv0, 0);
    int nv31 = 0;
    if (lane == 31) nv31 = (base + CHUNK < M) ? __ldg(&pair_idx[base + CHUNK]) : -3;
    const int nextk = __shfl_sync(FULL, nv31, 31);

    // --- per-lane scan of 8 items ---
    const int headkey = pk[0];
    int   cur = pk[0];
    float4 ea0 = sea[nk[0]];
    float c0 = ck[0];
    float ax = c0 * ea0.x, ay = c0 * ea0.y, az = c0 * ea0.z, aw = c0 * ea0.w, as = c0;
    int   segcnt = 0;
    int   hkey = 0;
    float hx = 0.f, hy = 0.f, hz = 0.f, hw = 0.f, hs = 0.f;

    #pragma unroll
    for (int k = 1; k < IPL; k++) {
        int  key = pk[k];
        bool neq = (key != cur);
        // interior segment (2nd+ change): fully inside lane => exclusive store
        int doflush = (int)(neq & (segcnt > 0) & (as != 0.f));
        pred_flush(doflush, cur, ax, ay, az, aw, as);
        // stash first segment partial (connects left)
        bool stash = neq & (segcnt == 0);
        hkey = stash ? cur : hkey;
        hx = stash ? ax : hx; hy = stash ? ay : hy; hz = stash ? az : hz;
        hw = stash ? aw : hw; hs = stash ? as : hs;
        segcnt += (int)neq;
        float  cc = ck[k];
        float4 e  = sea[nk[k]];
        ax = fmaf(cc, e.x, neq ? 0.f : ax);
        ay = fmaf(cc, e.y, neq ? 0.f : ay);
        az = fmaf(cc, e.z, neq ? 0.f : az);
        aw = fmaf(cc, e.w, neq ? 0.f : aw);
        as = cc + (neq ? 0.f : as);
        cur = key;
    }
    const int tkey = cur;   // trailing key; (ax..as) = trailing partial

    // --- Kogge-Stone with warp-uniform truncation (segments are short) ---
    KS_STEP(1);
    KS_STEP(2);
    {
        int k4 = __shfl_up_sync(FULL, tkey, 4);
        if (__any_sync(FULL, (lane >= 4) && (k4 == tkey))) {
            KS_STEP(4);
            int k8 = __shfl_up_sync(FULL, tkey, 8);
            if (__any_sync(FULL, (lane >= 8) && (k8 == tkey))) {
                KS_STEP(8);
                KS_STEP(16);
            }
        }
    }

    int   tkp = __shfl_up_sync(FULL, tkey, 1);
    float ypx = __shfl_up_sync(FULL, ax, 1);
    float ypy = __shfl_up_sync(FULL, ay, 1);
    float ypz = __shfl_up_sync(FULL, az, 1);
    float ypw = __shfl_up_sync(FULL, aw, 1);
    float yps = __shfl_up_sync(FULL, as, 1);
    int   hkn = __shfl_down_sync(FULL, headkey, 1);

    // 1) head-close flush: first segment of this lane closed inside the lane.
    if (segcnt > 0) {
        bool cge = (lane > 0) && (hkey == tkp);
        float fx = hx + (cge ? ypx : 0.f);
        float fy = hy + (cge ? ypy : 0.f);
        float fz = hz + (cge ? ypz : 0.f);
        float fw = hw + (cge ? ypw : 0.f);
        float fs = hs + (cge ? yps : 0.f);
        if (fs != 0.f)
            flush_maybe_shared(hkey == prevk, hkey, fx, fy, fz, fw, fs);
    }
    // 2) trailing-chain close: this lane holds the full within-chunk sum for tkey.
    bool closes = (lane == 31) || (hkn != tkey);
    if (closes && as != 0.f) {
        bool shared_seg = (tkey == prevk) || ((lane == 31) && (tkey == nextk));
        flush_maybe_shared(shared_seg, tkey, ax, ay, az, aw, as);
    }
}

// ---------------------------------------------------------------------------
// Pass 2: expand g/s -> 32 channels, plane-major coalesced float4 stores.
// 256-thread blocks, 2 pairs/thread -> high occupancy for latency hiding.
// ---------------------------------------------------------------------------
#define BT2 256
#define PP  2

__global__ void __launch_bounds__(BT2) pass2_kernel(
    const float* __restrict__ W,   // [32,4]
    const float* __restrict__ b,   // [32]
    float* __restrict__ out)       // [32, 768*768]
{
    __shared__ float sW[NH * 4];
    __shared__ float sb[NH];
    int tid = threadIdx.x;
    if (tid < NH * 4) sW[tid] = W[tid];
    if (tid < NH)     sb[tid] = b[tid];
    __syncthreads();

    int p = (blockIdx.x * BT2 + tid) * PP;
    float4 g0 = __ldcs(&D_G[p + 0]);
    float4 g1 = __ldcs(&D_G[p + 1]);
    float2 sv = __ldcs(reinterpret_cast<const float2*>(D_S) + (p >> 1));

    #pragma unroll 8
    for (int h = 0; h < NH; h++) {
        float w0 = sW[4 * h + 0], w1 = sW[4 * h + 1];
        float w2 = sW[4 * h + 2], w3 = sW[4 * h + 3];
        float bh = sb[h];
        float2 r;
        r.x = fmaf(g0.x, w0, fmaf(g0.y, w1, fmaf(g0.z, w2, fmaf(g0.w, w3, sv.x * bh))));
        r.y = fmaf(g1.x, w0, fmaf(g1.y, w1, fmaf(g1.z, w2, fmaf(g1.w, w3, sv.y * bh))));
        __stcs(reinterpret_cast<float2*>(out) + ((h * NN + p) >> 1), r);
    }
}

// ---------------------------------------------------------------------------
// kernel_launch
// ---------------------------------------------------------------------------
extern "C" void kernel_launch(void* const* d_in, const int* in_sizes, int n_in,
                              void* d_out, int out_size)
{
    const float* edge_attr = nullptr;
    const float* W = nullptr;
    const float* b = nullptr;
    const int*   pair = nullptr;
    const int*   node = nullptr;
    const float* coeff = nullptr;
    int M = 0;
    int bigSeen = 0;

    for (int i = 0; i < n_in; i++) {
        int s = in_sizes[i];
        if (s == NNODES * 4)      edge_attr = (const float*)d_in[i];
        else if (s == NH * 4)     W = (const float*)d_in[i];
        else if (s == NH)         b = (const float*)d_in[i];
        else if (s >= 1000000) {
            if (bigSeen == 0)      pair  = (const int*)d_in[i];
            else if (bigSeen == 1) node  = (const int*)d_in[i];
            else if (bigSeen == 2) { coeff = (const float*)d_in[i]; M = s; }
            bigSeen++;
        }
    }

    // Zero scratch with a graph-capturable memset node (no allocation).
    void* bufp = nullptr;
    cudaGetSymbolAddress(&bufp, d_buf);
    cudaMemsetAsync(bufp, 0, sizeof(float) * (size_t)NN * 5);

    int grid1 = (M + TILE - 1) / TILE;   // ~4883
    pass1_kernel<<<grid1, BT>>>(pair, node, coeff, edge_attr, M);

    int grid2 = NN / (BT2 * PP);         // 1152
    pass2_kernel<<<grid2, BT2>>>(W, b, (float*)d_out);
}